// round 1
// baseline (speedup 1.0000x reference)
#include <cuda_runtime.h>

// Problem constants (fixed by the reference)
#define BB 16
#define TT 4096
#define DD 64
#define KK 1024
#define NROWS (BB * TT)          // 65536 rows
#define BETA_ 0.25

// Tiling
#define TK 64                    // codes per SMEM tile (64*64*4B = 16KB)
#define NTILES (KK / TK)         // 16
#define THREADS 64               // threads per block (1 row per thread)
#define NBLOCKS (NROWS / THREADS)// 1024 blocks -> ~6.9 blocks/SM, balanced

// Scratch (no allocations allowed in kernel_launch)
__device__ float  g_ne[KK];
__device__ double g_partials[NBLOCKS];

// --- Kernel 0: per-code squared norms  ne[k] = sum_i e[k,i]^2 -------------
__global__ void ne_kernel(const float* __restrict__ emb) {
    int k = blockIdx.x * blockDim.x + threadIdx.x;
    if (k < KK) {
        const float* e = emb + k * DD;
        float s0 = 0.f, s1 = 0.f, s2 = 0.f, s3 = 0.f;
        #pragma unroll
        for (int i = 0; i < DD; i += 4) {
            s0 = fmaf(e[i + 0], e[i + 0], s0);
            s1 = fmaf(e[i + 1], e[i + 1], s1);
            s2 = fmaf(e[i + 2], e[i + 2], s2);
            s3 = fmaf(e[i + 3], e[i + 3], s3);
        }
        g_ne[k] = (s0 + s1) + (s2 + s3);
    }
}

// --- Kernel 1: argmin over codebook + z_q gather + loss partials ----------
__global__ void __launch_bounds__(THREADS)
vq_kernel(const float* __restrict__ z,
          const float* __restrict__ emb,
          float* __restrict__ out) {
    __shared__ float  se[TK * DD];   // 16 KB codebook tile
    __shared__ double sred[2];

    const int row = blockIdx.x * THREADS + threadIdx.x;  // < NROWS always

    // Load this thread's z row (64 floats) into registers
    float4 zv[16];
    {
        const float4* zr = reinterpret_cast<const float4*>(z) + row * (DD / 4);
        #pragma unroll
        for (int i = 0; i < 16; i++) zv[i] = zr[i];
    }

    // ||z||^2 (constant per row; exact accumulation order is argmin-neutral)
    float nz;
    {
        float s0 = 0.f, s1 = 0.f, s2 = 0.f, s3 = 0.f;
        #pragma unroll
        for (int i = 0; i < 16; i++) {
            s0 = fmaf(zv[i].x, zv[i].x, s0);
            s1 = fmaf(zv[i].y, zv[i].y, s1);
            s2 = fmaf(zv[i].z, zv[i].z, s2);
            s3 = fmaf(zv[i].w, zv[i].w, s3);
        }
        nz = (s0 + s1) + (s2 + s3);
    }

    float best = 3.4e38f;
    int   bidx = 0;

    for (int t = 0; t < NTILES; ++t) {
        __syncthreads();  // protect previous tile consumers
        // Cooperative tile load: 64 codes * 64 floats = 1024 float4
        {
            const float4* src = reinterpret_cast<const float4*>(emb) + t * (TK * DD / 4);
            float4* dst = reinterpret_cast<float4*>(se);
            #pragma unroll
            for (int i = 0; i < (TK * DD / 4) / THREADS; i++)
                dst[threadIdx.x + i * THREADS] = src[threadIdx.x + i * THREADS];
        }
        __syncthreads();

        #pragma unroll 2
        for (int k = 0; k < TK; k++) {
            const float4* e4 = reinterpret_cast<const float4*>(se + k * DD);
            float d0 = 0.f, d1 = 0.f, d2 = 0.f, d3 = 0.f;
            #pragma unroll
            for (int i = 0; i < 16; i++) {
                float4 ev = e4[i];   // warp-uniform address -> LDS broadcast
                d0 = fmaf(zv[i].x, ev.x, d0);
                d1 = fmaf(zv[i].y, ev.y, d1);
                d2 = fmaf(zv[i].z, ev.z, d2);
                d3 = fmaf(zv[i].w, ev.w, d3);
            }
            float dot = (d0 + d1) + (d2 + d3);
            int   gk  = t * TK + k;
            // Mirror reference rounding: a = fl(nz + ne); dist = fl(a - 2*dot)
            float a    = nz + g_ne[gk];
            float dist = fmaf(-2.f, dot, a);
            if (dist < best) { best = dist; bidx = gk; }  // strict < == lowest-index tie-break
        }
    }

    // idx output (as float, output buffer is fp32)
    out[(size_t)NROWS * DD + 1 + row] = (float)bidx;

    // z_q = emb[bidx] gather (bitwise-exact vs reference) + loss partial
    double acc = 0.0;
    {
        const float4* eg = reinterpret_cast<const float4*>(emb) + bidx * (DD / 4);
        float4* oq = reinterpret_cast<float4*>(out) + row * (DD / 4);
        #pragma unroll
        for (int i = 0; i < 16; i++) {
            float4 ev = __ldg(&eg[i]);
            float dx = ev.x - zv[i].x;
            float dy = ev.y - zv[i].y;
            float dzc = ev.z - zv[i].z;
            float dw = ev.w - zv[i].w;
            acc += (double)dx * dx + (double)dy * dy
                 + (double)dzc * dzc + (double)dw * dw;
            oq[i] = ev;
        }
    }

    // Deterministic in-block reduction (fixed shuffle tree + fixed order)
    #pragma unroll
    for (int o = 16; o > 0; o >>= 1)
        acc += __shfl_down_sync(0xffffffffu, acc, o);
    int lane = threadIdx.x & 31, w = threadIdx.x >> 5;
    if (lane == 0) sred[w] = acc;
    __syncthreads();
    if (threadIdx.x == 0) g_partials[blockIdx.x] = sred[0] + sred[1];
}

// --- Kernel 2: deterministic fixed-tree reduction of loss partials --------
__global__ void loss_kernel(float* __restrict__ out) {
    __shared__ double sd[256];
    int tid = threadIdx.x;  // 256 threads
    double s = g_partials[tid] + g_partials[tid + 256]
             + g_partials[tid + 512] + g_partials[tid + 768];
    sd[tid] = s;
    __syncthreads();
    #pragma unroll
    for (int st = 128; st > 0; st >>= 1) {
        if (tid < st) sd[tid] += sd[tid + st];
        __syncthreads();
    }
    if (tid == 0) {
        // loss = sum_b (beta*mean_b + mean_b) = 1.25 * total / (T*D)
        out[(size_t)NROWS * DD] =
            (float)((1.0 + BETA_) * sd[0] / (double)(TT * DD));
    }
}

extern "C" void kernel_launch(void* const* d_in, const int* in_sizes, int n_in,
                              void* d_out, int out_size) {
    const float* z   = (const float*)d_in[0];   // [B, T, D] fp32
    const float* emb = (const float*)d_in[1];   // [K, D]    fp32
    float* out = (float*)d_out;                 // [z_q | loss | idx] fp32

    ne_kernel<<<KK / 64, 64>>>(emb);
    vq_kernel<<<NBLOCKS, THREADS>>>(z, emb, out);
    loss_kernel<<<1, 256>>>(out);
}

// round 2
// speedup vs baseline: 1.0600x; 1.0600x over previous
#include <cuda_runtime.h>

// Problem constants (fixed by the reference)
#define BB 16
#define TT 4096
#define DD 64
#define KK 1024
#define NROWS (BB * TT)           // 65536 rows
#define BETA_ 0.25

// Tiling
#define TK 64                     // codes per SMEM tile (64*64*4B = 16KB)
#define NTILES (KK / TK)          // 16
#define THREADS 64                // threads per block (1 row per thread)
#define NBLOCKS (NROWS / THREADS) // 1024 blocks

// Scratch (no allocations allowed in kernel_launch)
__device__ float  g_ne[KK];
__device__ double g_partials[NBLOCKS];

// Packed fp32x2 FMA (Blackwell FFMA2): two IEEE fp32 FMAs per instruction.
// ptxas never emits this from C++; inline PTX only.
__device__ __forceinline__ unsigned long long ffma2(unsigned long long a,
                                                    unsigned long long b,
                                                    unsigned long long c) {
    unsigned long long d;
    asm("fma.rn.f32x2 %0, %1, %2, %3;" : "=l"(d) : "l"(a), "l"(b), "l"(c));
    return d;
}

__device__ __forceinline__ void unpack2(unsigned long long v, float& lo, float& hi) {
    asm("mov.b64 {%0, %1}, %2;" : "=f"(lo), "=f"(hi) : "l"(v));
}

// --- Kernel 0: per-code squared norms  ne[k] = sum_i e[k,i]^2 -------------
__global__ void ne_kernel(const float* __restrict__ emb) {
    int k = blockIdx.x * blockDim.x + threadIdx.x;
    if (k < KK) {
        const float* e = emb + k * DD;
        float s0 = 0.f, s1 = 0.f, s2 = 0.f, s3 = 0.f;
        #pragma unroll
        for (int i = 0; i < DD; i += 4) {
            s0 = fmaf(e[i + 0], e[i + 0], s0);
            s1 = fmaf(e[i + 1], e[i + 1], s1);
            s2 = fmaf(e[i + 2], e[i + 2], s2);
            s3 = fmaf(e[i + 3], e[i + 3], s3);
        }
        g_ne[k] = (s0 + s1) + (s2 + s3);
    }
}

// --- Kernel 1: argmin over codebook + z_q gather + loss partials ----------
__global__ void __launch_bounds__(THREADS)
vq_kernel(const float* __restrict__ z,
          const float* __restrict__ emb,
          float* __restrict__ out) {
    __shared__ __align__(16) float se[TK * DD];  // 16 KB codebook tile
    __shared__ float  sne[TK];                   // ne tile (broadcast LDS)
    __shared__ double sred[2];

    const int row = blockIdx.x * THREADS + threadIdx.x;  // < NROWS always

    // Load this thread's z row (64 floats) as 32 packed f32x2 values.
    unsigned long long zp[32];
    {
        const ulonglong2* zr =
            reinterpret_cast<const ulonglong2*>(z + (size_t)row * DD);
        #pragma unroll
        for (int i = 0; i < 16; i++) {
            ulonglong2 v = zr[i];
            zp[2 * i + 0] = v.x;
            zp[2 * i + 1] = v.y;
        }
    }

    // ||z||^2 via two packed chains (bitwise == 4-way split (s0+s1)+(s2+s3))
    float nz;
    {
        unsigned long long a01 = 0ull, a23 = 0ull;
        #pragma unroll
        for (int i = 0; i < 16; i++) {
            a01 = ffma2(zp[2 * i + 0], zp[2 * i + 0], a01);
            a23 = ffma2(zp[2 * i + 1], zp[2 * i + 1], a23);
        }
        float s0, s1, s2, s3;
        unpack2(a01, s0, s1);
        unpack2(a23, s2, s3);
        nz = (s0 + s1) + (s2 + s3);
    }

    float best = 3.4e38f;
    int   bidx = 0;

    for (int t = 0; t < NTILES; ++t) {
        __syncthreads();  // protect previous tile consumers
        // Cooperative tile load: 64 codes * 64 floats = 1024 float4
        {
            const float4* src =
                reinterpret_cast<const float4*>(emb) + t * (TK * DD / 4);
            float4* dst = reinterpret_cast<float4*>(se);
            #pragma unroll
            for (int i = 0; i < (TK * DD / 4) / THREADS; i++)
                dst[threadIdx.x + i * THREADS] = src[threadIdx.x + i * THREADS];
            sne[threadIdx.x] = g_ne[t * TK + threadIdx.x];
        }
        __syncthreads();

        #pragma unroll 4
        for (int k = 0; k < TK; k++) {
            const ulonglong2* e2 =
                reinterpret_cast<const ulonglong2*>(se + k * DD);
            unsigned long long a01 = 0ull, a23 = 0ull;
            #pragma unroll
            for (int i = 0; i < 16; i++) {
                ulonglong2 ev = e2[i];   // warp-uniform -> LDS broadcast
                a01 = ffma2(zp[2 * i + 0], ev.x, a01);
                a23 = ffma2(zp[2 * i + 1], ev.y, a23);
            }
            float d0, d1, d2, d3;
            unpack2(a01, d0, d1);
            unpack2(a23, d2, d3);
            float dot = (d0 + d1) + (d2 + d3);
            // Mirror reference rounding: a = fl(nz + ne); dist = fl(a - 2*dot)
            float a    = nz + sne[k];
            float dist = fmaf(-2.f, dot, a);
            if (dist < best) { best = dist; bidx = t * TK + k; }  // strict <
        }
    }

    // idx output (as float, output buffer is fp32)
    out[(size_t)NROWS * DD + 1 + row] = (float)bidx;

    // z_q = emb[bidx] gather (bitwise-exact vs reference) + loss partial
    double acc = 0.0;
    {
        const float4* eg = reinterpret_cast<const float4*>(emb) + bidx * (DD / 4);
        const float*  zr = z + (size_t)row * DD;
        float4* oq = reinterpret_cast<float4*>(out) + row * (DD / 4);
        #pragma unroll
        for (int i = 0; i < 16; i++) {
            float4 ev = __ldg(&eg[i]);
            float dx = ev.x - zr[4 * i + 0];
            float dy = ev.y - zr[4 * i + 1];
            float dzc = ev.z - zr[4 * i + 2];
            float dw = ev.w - zr[4 * i + 3];
            acc += (double)dx * dx + (double)dy * dy
                 + (double)dzc * dzc + (double)dw * dw;
            oq[i] = ev;
        }
    }

    // Deterministic in-block reduction (fixed shuffle tree + fixed order)
    #pragma unroll
    for (int o = 16; o > 0; o >>= 1)
        acc += __shfl_down_sync(0xffffffffu, acc, o);
    int lane = threadIdx.x & 31, w = threadIdx.x >> 5;
    if (lane == 0) sred[w] = acc;
    __syncthreads();
    if (threadIdx.x == 0) g_partials[blockIdx.x] = sred[0] + sred[1];
}

// --- Kernel 2: deterministic fixed-tree reduction of loss partials --------
__global__ void loss_kernel(float* __restrict__ out) {
    __shared__ double sd[256];
    int tid = threadIdx.x;  // 256 threads
    double s = g_partials[tid] + g_partials[tid + 256]
             + g_partials[tid + 512] + g_partials[tid + 768];
    sd[tid] = s;
    __syncthreads();
    #pragma unroll
    for (int st = 128; st > 0; st >>= 1) {
        if (tid < st) sd[tid] += sd[tid + st];
        __syncthreads();
    }
    if (tid == 0) {
        // loss = sum_b (beta*mean_b + mean_b) = 1.25 * total / (T*D)
        out[(size_t)NROWS * DD] =
            (float)((1.0 + BETA_) * sd[0] / (double)(TT * DD));
    }
}

extern "C" void kernel_launch(void* const* d_in, const int* in_sizes, int n_in,
                              void* d_out, int out_size) {
    const float* z   = (const float*)d_in[0];   // [B, T, D] fp32
    const float* emb = (const float*)d_in[1];   // [K, D]    fp32
    float* out = (float*)d_out;                 // [z_q | loss | idx] fp32

    ne_kernel<<<KK / 64, 64>>>(emb);
    vq_kernel<<<NBLOCKS, THREADS>>>(z, emb, out);
    loss_kernel<<<1, 256>>>(out);
}